// round 13
// baseline (speedup 1.0000x reference)
#include <cuda_runtime.h>

#define FULL_MASK 0xffffffffu

__global__ void ord_zero_kernel(float* out) {
    if (threadIdx.x == 0 && blockIdx.x == 0) *out = 0.0f;
}

__device__ __forceinline__ float ex2f(float x) {
    float y; asm("ex2.approx.ftz.f32 %0, %1;" : "=f"(y) : "f"(x)); return y;
}
__device__ __forceinline__ float lg2f(float x) {
    float y; asm("lg2.approx.ftz.f32 %0, %1;" : "=f"(y) : "f"(x)); return y;
}

#define NEG_LOG2E (-1.4426950408889634f)

// Process one row held in registers (v0,v1 = 8 contiguous elems per lane, t = target).
__device__ __forceinline__ void process_row(
    float4 v0, float4 v1, int t,
    int lane, bool last_lane,
    float& acc_r, float& acc_l2)
{
    // lane total via tree (shorter critical path into the scan)
    float t01 = v0.x + v0.y, t23 = v0.z + v0.w;
    float t45 = v1.x + v1.y, t67 = v1.z + v1.w;
    float tot = (t01 + t23) + (t45 + t67);

    // warp inclusive scan of lane totals
    float s = tot;
    #pragma unroll
    for (int o = 1; o < 32; o <<= 1) {
        float n = __shfl_up_sync(FULL_MASK, s, o);
        if (lane >= o) s += n;
    }
    const float cbase = s - tot;       // exclusive prefix for this lane
    const int   kt    = t - 8 * lane;  // i < kt  <=>  k < t

    // serial chain of cumulative values, cbase folded in
    float c0 = cbase + v0.x;
    float c1 = c0 + v0.y;
    float c2 = c1 + v0.z;
    float c3 = c2 + v0.w;
    float c4 = c3 + v1.x;
    float c5 = c4 + v1.y;
    float c6 = c5 + v1.z;
    float c7 = c6 + v1.w;

    float prod = 1.0f;
    float cl[8] = {c0, c1, c2, c3, c4, c5, c6, c7};

    #pragma unroll
    for (int i = 0; i < 8; ++i) {
        float c = cl[i];
        float u = (i < kt) ? c : -c;
        float e = ex2f(fabsf(c) * NEG_LOG2E);   // e^{-|c|}
        if (i == 7) {                            // exclude k == 255 (lane 31 only)
            u = last_lane ? -1.0f : u;
            e = last_lane ?  0.0f : e;
        }
        acc_r += fmaxf(u, 0.0f);
        prod   = fmaf(prod, e, prod);            // prod *= (1 + e)
    }
    acc_l2 += lg2f(prod);
}

// Persistent single-wave grid: 740 CTAs (5/SM x 148 SMs). Main loop has NO
// bounds checks; remainder rows handled in a guarded epilogue.
__global__ __launch_bounds__(256, 5) void ord_loss_kernel(
    const float* __restrict__ logits,
    const long long* __restrict__ targets,
    float* __restrict__ out,
    int B)
{
    const int lane  = threadIdx.x & 31;
    const int wib   = threadIdx.x >> 5;
    const int gwarp = blockIdx.x * (blockDim.x >> 5) + wib;
    const int nwarp = gridDim.x * (blockDim.x >> 5);
    const bool last_lane = (lane == 31);

    float acc_r = 0.0f, acc_l2 = 0.0f;

    const float4* base4 = reinterpret_cast<const float4*>(logits);
    const int iters = B / nwarp;                 // same for every warp

    // running pointers (row stride = 64 float4)
    const float4*    px  = base4 + ((size_t)gwarp << 6) + (lane << 1);
    const float4*    py  = px + ((size_t)nwarp << 6);
    const long long* tqx = targets + gwarp;
    const long long* tqy = tqx + nwarp;
    const size_t     pstep = (size_t)nwarp << 7;   // 2*nwarp rows, in float4 units
    const size_t     tstep = (size_t)nwarp << 1;   // 2*nwarp targets

    float4 x0, x1, y0, y1;
    int tx = 0, ty = 0;

    if (iters > 0) { x0 = px[0]; x1 = px[1]; tx = *(const int*)tqx; }
    if (iters > 1) { y0 = py[0]; y1 = py[1]; ty = *(const int*)tqy; }

    int it = 0;
    while (it < iters) {
        // ---- X ----
        {
            float4 v0 = x0, v1 = x1; int t = tx;
            if (it + 2 < iters) {                 // uniform branch (same for all warps)
                px += pstep; tqx += tstep;
                x0 = px[0]; x1 = px[1]; tx = *(const int*)tqx;
            }
            process_row(v0, v1, t, lane, last_lane, acc_r, acc_l2);
        }
        if (++it >= iters) break;
        // ---- Y ----
        {
            float4 v0 = y0, v1 = y1; int t = ty;
            if (it + 2 < iters) {
                py += pstep; tqy += tstep;
                y0 = py[0]; y1 = py[1]; ty = *(const int*)tqy;
            }
            process_row(v0, v1, t, lane, last_lane, acc_r, acc_l2);
        }
        ++it;
    }

    // epilogue: remainder rows (B % nwarp of them)
    {
        const int rrow = iters * nwarp + gwarp;
        if (rrow < B) {
            const float4* rp = base4 + ((size_t)rrow << 6);
            float4 v0 = rp[2 * lane];
            float4 v1 = rp[2 * lane + 1];
            int t = *(const int*)(targets + rrow);
            process_row(v0, v1, t, lane, last_lane, acc_r, acc_l2);
        }
    }

    float r = fmaf(0.69314718055994531f, acc_l2, acc_r);

    #pragma unroll
    for (int o = 16; o; o >>= 1) r += __shfl_xor_sync(FULL_MASK, r, o);

    __shared__ float ws[8];
    if (lane == 0) ws[wib] = r;
    __syncthreads();
    if (threadIdx.x == 0) {
        float ssum = 0.0f;
        #pragma unroll
        for (int i = 0; i < 8; ++i) ssum += ws[i];
        atomicAdd(out, ssum * (1.0f / (float)B));
    }
}

extern "C" void kernel_launch(void* const* d_in, const int* in_sizes, int n_in,
                              void* d_out, int out_size)
{
    const float*     logits  = (const float*)d_in[0];
    const long long* targets = (const long long*)d_in[1];
    float*           out     = (float*)d_out;

    const int B = in_sizes[1];

    ord_zero_kernel<<<1, 32>>>(out);
    ord_loss_kernel<<<740, 256>>>(logits, targets, out, B);   // 5 CTAs/SM x 148 SMs, single wave
}